// round 17
// baseline (speedup 1.0000x reference)
#include <cuda_runtime.h>
#include <cuda_fp16.h>

// out[b,o] = max_k min(x[b,k], w[k,o])  (STE forward == hard max-min)
// x: [B,512] f32 uniform[0,1), w: [512,512] f32, out f32. B = 1024.
//
// Candidate algorithm (R6 ladder, measured best): per b-row, tier-1 cands
// x >= 0.875 (~64), tier-2 [0.78,0.875) for certificate failures (~3e-4),
// exact fp32 scan last resort (any-distribution correctness).
//
// R17: cp.async (LDGSTS) staging. Tier-1 row loads are contiguous 1KB rows;
// each thread issues cnt1 8-byte cp.asyncs for ITS OWN slice of every row
// (no dest registers -> all ~64 in flight), ONE cp.async.wait_all, then
// computes purely from smem. Collapses R6's ~8 serial L2 waits to 1.
// Thread reads back exactly what it staged -> no block barrier needed.
// Rows beyond STAGE (P~50%, mean ~3) take a short direct-LDG tail.

#define KDIM 512
#define ODIM 512
#define O2   256          // half2 pairs along o; packed w row = 1KB = 128 uint2
#define NT   128          // thread owns outputs [4t, 4t+4)
#define CUT1 0.875f
#define CUT2 0.78f
#define EPS  1e-3f
#define C1MAX 160
#define C2MAX 160
#define STAGE 64          // staged tier-1 rows (64KB smem)

__device__ __half2 g_wh[KDIM * O2];   // [k][o2]; row k at byte k*1024

__global__ __launch_bounds__(512)
void packw_kernel(const float* __restrict__ w)
{
    int i = blockIdx.x * blockDim.x + threadIdx.x;   // 65536 float4 units
    float4 v = reinterpret_cast<const float4*>(w)[i];
    __half2 h0 = __floats2half2_rn(v.x, v.y);
    __half2 h1 = __floats2half2_rn(v.z, v.w);
    uint2 pk;
    pk.x = *reinterpret_cast<unsigned*>(&h0);
    pk.y = *reinterpret_cast<unsigned*>(&h1);
    reinterpret_cast<uint2*>(g_wh)[i] = pk;
}

__global__ __launch_bounds__(NT)
void maxmin_kernel(const float* __restrict__ x,
                   const float* __restrict__ w,
                   float* __restrict__ out)
{
    extern __shared__ char stg[];     // [STAGE][1024]: staged w rows
    __shared__ float xs[KDIM];
    __shared__ uint2 c1[C1MAX];       // {half2-splat(x) bits, k (row index)}
    __shared__ uint2 c2[C2MAX];
    __shared__ int   s_n1, s_n2, s_ovf;

    const int b   = blockIdx.x;
    const int tid = threadIdx.x;      // owns outputs 4*tid .. 4*tid+3

    if (tid == 0) { s_n1 = 0; s_n2 = 0; s_ovf = 0; }
    __syncthreads();

    // ---- stage x row (fp32, for fallback) + threshold selection ----
    {
        float4 v = reinterpret_cast<const float4*>(x + (size_t)b * KDIM)[tid];
        reinterpret_cast<float4*>(xs)[tid] = v;
        float e[4] = {v.x, v.y, v.z, v.w};
#pragma unroll
        for (int q = 0; q < 4; q++) {
            float xv = e[q];
            if (xv >= CUT2) {
                int k = tid * 4 + q;
                __half   h  = __float2half_rn(xv);
                __half2  h2 = __halves2half2(h, h);
                unsigned hb = *reinterpret_cast<const unsigned*>(&h2);
                if (xv >= CUT1) {
                    int p = atomicAdd(&s_n1, 1);
                    if (p < C1MAX) c1[p] = make_uint2(hb, (unsigned)k);
                    else           s_ovf = 1;
                } else {
                    int p = atomicAdd(&s_n2, 1);
                    if (p < C2MAX) c2[p] = make_uint2(hb, (unsigned)k);
                    else           s_ovf = 1;
                }
            }
        }
    }
    __syncthreads();

    const int cnt1 = s_n1;
    const int cnt2 = (s_n2 < C2MAX) ? s_n2 : C2MAX;
    const int ovf  = s_ovf;
    const int s1   = (cnt1 < STAGE) ? cnt1 : STAGE;

    const uint2* wu = reinterpret_cast<const uint2*>(g_wh);
    const char*  gw = reinterpret_cast<const char*>(g_wh);

    // ---- issue cp.async: this thread's 8B slice of every staged row ----
    // (no dest regs -> all s1 loads in flight; one wait; no barrier needed
    //  because each thread reads back only its own staged bytes)
    unsigned stg_base;
    {
        void* p = stg;
        stg_base = (unsigned)__cvta_generic_to_shared(p);
    }
    if (!ovf) {
#pragma unroll 4
        for (int t = 0; t < s1; t++) {
            uint2 c = c1[t];
            unsigned    sa = stg_base + t * 1024 + tid * 8;
            const char* ga = gw + ((size_t)c.y << 10) + tid * 8;
            asm volatile("cp.async.ca.shared.global [%0], [%1], 8;\n"
                         :: "r"(sa), "l"(ga) : "memory");
        }
        asm volatile("cp.async.wait_all;\n" ::: "memory");
    }

    __half2 a0 = __float2half2_rn(0.0f);    // inputs >= 0: 0 is a safe -inf
    __half2 a1 = a0;

    if (!ovf) {
        // ---- tier-1 compute: pure smem, ILP-4 ----
        const uint2* sr = reinterpret_cast<const uint2*>(stg) + tid;   // +128/row
        int t = 0;
        for (; t + 4 <= s1; t += 4) {
            uint2 w0 = sr[(t + 0) * 128];
            uint2 w1 = sr[(t + 1) * 128];
            uint2 w2 = sr[(t + 2) * 128];
            uint2 w3 = sr[(t + 3) * 128];
            uint2 e0 = c1[t + 0], e1 = c1[t + 1], e2 = c1[t + 2], e3 = c1[t + 3];
            __half2 xv;
            xv = *reinterpret_cast<__half2*>(&e0.x);
            a0 = __hmax2(a0, __hmin2(xv, *reinterpret_cast<__half2*>(&w0.x)));
            a1 = __hmax2(a1, __hmin2(xv, *reinterpret_cast<__half2*>(&w0.y)));
            xv = *reinterpret_cast<__half2*>(&e1.x);
            a0 = __hmax2(a0, __hmin2(xv, *reinterpret_cast<__half2*>(&w1.x)));
            a1 = __hmax2(a1, __hmin2(xv, *reinterpret_cast<__half2*>(&w1.y)));
            xv = *reinterpret_cast<__half2*>(&e2.x);
            a0 = __hmax2(a0, __hmin2(xv, *reinterpret_cast<__half2*>(&w2.x)));
            a1 = __hmax2(a1, __hmin2(xv, *reinterpret_cast<__half2*>(&w2.y)));
            xv = *reinterpret_cast<__half2*>(&e3.x);
            a0 = __hmax2(a0, __hmin2(xv, *reinterpret_cast<__half2*>(&w3.x)));
            a1 = __hmax2(a1, __hmin2(xv, *reinterpret_cast<__half2*>(&w3.y)));
        }
        for (; t < s1; t++) {
            uint2 wv = sr[t * 128];
            uint2 e  = c1[t];
            __half2 xv = *reinterpret_cast<__half2*>(&e.x);
            a0 = __hmax2(a0, __hmin2(xv, *reinterpret_cast<__half2*>(&wv.x)));
            a1 = __hmax2(a1, __hmin2(xv, *reinterpret_cast<__half2*>(&wv.y)));
        }
        // ---- rare tail: candidates beyond STAGE via direct LDG ----
#pragma unroll 1
        for (int tt = STAGE; tt < cnt1; tt++) {
            uint2 c = c1[tt];
            uint2 wv = wu[(size_t)c.y * 128 + tid];
            __half2 xv = *reinterpret_cast<__half2*>(&c.x);
            a0 = __hmax2(a0, __hmin2(xv, *reinterpret_cast<__half2*>(&wv.x)));
            a1 = __hmax2(a1, __hmin2(xv, *reinterpret_cast<__half2*>(&wv.y)));
        }
    }

    float r[4];
    r[0] = __low2float(a0); r[1] = __high2float(a0);
    r[2] = __low2float(a1); r[3] = __high2float(a1);

    // ---- tier-2 extension (rare; any of 4 outputs failing certificate) ----
    bool fail1 = false;
#pragma unroll
    for (int j = 0; j < 4; j++) fail1 |= (r[j] < CUT1 + EPS);

    if (!ovf && fail1) {
#pragma unroll 1
        for (int t = 0; t < cnt2; t++) {
            uint2 c = c2[t];
            uint2 wv = wu[(size_t)c.y * 128 + tid];
            __half2 xv = *reinterpret_cast<__half2*>(&c.x);
            a0 = __hmax2(a0, __hmin2(xv, *reinterpret_cast<__half2*>(&wv.x)));
            a1 = __hmax2(a1, __hmin2(xv, *reinterpret_cast<__half2*>(&wv.y)));
        }
        r[0] = __low2float(a0); r[1] = __high2float(a0);
        r[2] = __low2float(a1); r[3] = __high2float(a1);
    }

    // ---- exact fp32 fallback (essentially never for uniform inputs) ----
#pragma unroll 1
    for (int j = 0; j < 4; j++) {
        if (ovf || r[j] < CUT2 + EPS) {
            int o = tid * 4 + j;
            float v = 0.0f;
#pragma unroll 1
            for (int k = 0; k < KDIM; k += 4) {
                float m0 = fminf(xs[k],     w[(size_t)(k)     * ODIM + o]);
                float m1 = fminf(xs[k + 1], w[(size_t)(k + 1) * ODIM + o]);
                float m2 = fminf(xs[k + 2], w[(size_t)(k + 2) * ODIM + o]);
                float m3 = fminf(xs[k + 3], w[(size_t)(k + 3) * ODIM + o]);
                v = fmaxf(v, fmaxf(fmaxf(m0, m1), fmaxf(m2, m3)));
            }
            r[j] = v;
        }
    }

    reinterpret_cast<float4*>(out + (size_t)b * ODIM)[tid] =
        make_float4(r[0], r[1], r[2], r[3]);
}

extern "C" void kernel_launch(void* const* d_in, const int* in_sizes, int n_in,
                              void* d_out, int out_size)
{
    const float* x = (const float*)d_in[0];   // [B, 512]
    const float* w = (const float*)d_in[1];   // [512, 512]
    float* out = (float*)d_out;

    int B = in_sizes[0] / KDIM;               // 1024

    const int stage_bytes = STAGE * 1024;     // 64KB dynamic smem
    cudaFuncSetAttribute(maxmin_kernel,
                         cudaFuncAttributeMaxDynamicSharedMemorySize,
                         stage_bytes);

    packw_kernel<<<128, 512>>>(w);
    maxmin_kernel<<<B, NT, stage_bytes>>>(x, w, out);
}